// round 2
// baseline (speedup 1.0000x reference)
#include <cuda_runtime.h>

// Fused 2-layer MLP:
//   h[b,f]  = relu( dot(inputs[b,f,:], W1[f,:]) + b1[f] )   (f=256, i=128)
//   out[b,o] = relu( dot(h[b,:], W2[o,:]) + b2[o] )          (o=128)
// B = in_sizes[0]/(256*128) (8192 in this problem). HBM-bound on the 1 GiB
// input stream; stage-2 compute hides under the HBM wait of co-resident CTAs.
//
// One CTA (256 threads = 8 warps) processes NB=4 consecutive batch rows:
//  - Stage 1: warp w owns f in [32w, 32w+32). Per f: load W1 row once (float4/lane,
//    512 B coalesced), dot against NB input rows, butterfly reduce, lane 0 -> smem.
//  - Stage 2: warp w owns o = w, w+8, ...  Per o: load W2 row once (2 float4/lane,
//    1 KB contiguous), dot against NB h vectors from smem, reduce, lane 0 writes.
// Weight rows are register-reused across the NB batches -> L1 traffic ~1.2x input bytes.

#define NB 4

__global__ __launch_bounds__(256) void fused_mlp_kernel(
    const float* __restrict__ in,  const float* __restrict__ W1,
    const float* __restrict__ b1,  const float* __restrict__ W2,
    const float* __restrict__ b2,  float* __restrict__ out,
    int B)
{
    __shared__ float h_s[NB][256];

    const int tid  = threadIdx.x;
    const int lane = tid & 31;
    const int warp = tid >> 5;
    const long long b0 = (long long)blockIdx.x * NB;

    // batch-validity mask for the tail CTA (no-op when B % NB == 0)
    bool valid[NB];
    #pragma unroll
    for (int nb = 0; nb < NB; ++nb) valid[nb] = (b0 + nb) < B;

    const float4* __restrict__ W1v = (const float4*)W1;

    // ------------------- Stage 1 -------------------
    #pragma unroll 2
    for (int k = 0; k < 32; ++k) {
        const int f = warp * 32 + k;
        const float4 w = W1v[f * 32 + lane];

        float s[NB];
        #pragma unroll
        for (int nb = 0; nb < NB; ++nb) {
            if (valid[nb]) {
                const float4* __restrict__ inb =
                    (const float4*)(in + (b0 + nb) * (256LL * 128));
                const float4 x = inb[f * 32 + lane];
                s[nb] = x.x * w.x + x.y * w.y + x.z * w.z + x.w * w.w;
            } else {
                s[nb] = 0.0f;
            }
        }

        #pragma unroll
        for (int off = 16; off > 0; off >>= 1) {
            #pragma unroll
            for (int nb = 0; nb < NB; ++nb)
                s[nb] += __shfl_xor_sync(0xFFFFFFFFu, s[nb], off);
        }

        if (lane == 0) {
            const float bb = b1[f];
            #pragma unroll
            for (int nb = 0; nb < NB; ++nb)
                h_s[nb][f] = fmaxf(s[nb] + bb, 0.0f);
        }
    }
    __syncthreads();

    // ------------------- Stage 2 -------------------
    #pragma unroll
    for (int o = warp; o < 128; o += 8) {
        const float4* __restrict__ w2r = (const float4*)(W2 + o * 256);
        const float4 wa = w2r[lane];
        const float4 wb = w2r[lane + 32];

        float s[NB];
        #pragma unroll
        for (int nb = 0; nb < NB; ++nb) {
            const float4* __restrict__ hv = (const float4*)h_s[nb];
            const float4 xa = hv[lane];
            const float4 xb = hv[lane + 32];
            s[nb] = wa.x * xa.x + wa.y * xa.y + wa.z * xa.z + wa.w * xa.w
                  + wb.x * xb.x + wb.y * xb.y + wb.z * xb.z + wb.w * xb.w;
        }

        #pragma unroll
        for (int off = 16; off > 0; off >>= 1) {
            #pragma unroll
            for (int nb = 0; nb < NB; ++nb)
                s[nb] += __shfl_xor_sync(0xFFFFFFFFu, s[nb], off);
        }

        if (lane == 0) {
            const float bb = b2[o];
            #pragma unroll
            for (int nb = 0; nb < NB; ++nb)
                if (valid[nb])
                    out[(b0 + nb) * 128 + o] = fmaxf(s[nb] + bb, 0.0f);
        }
    }
}

extern "C" void kernel_launch(void* const* d_in, const int* in_sizes, int n_in,
                              void* d_out, int out_size)
{
    const float* in = (const float*)d_in[0];   // [B, 256, 128] fp32
    const float* W1 = (const float*)d_in[1];   // [256, 128]
    const float* b1 = (const float*)d_in[2];   // [256]
    const float* W2 = (const float*)d_in[3];   // [128, 256]
    const float* b2 = (const float*)d_in[4];   // [128]
    float* out = (float*)d_out;                // [B, 128]

    const int B = in_sizes[0] / (256 * 128);
    const int grid = (B + NB - 1) / NB;

    fused_mlp_kernel<<<grid, 256>>>(in, W1, b1, W2, b2, out, B);
}

// round 3
// speedup vs baseline: 1.0454x; 1.0454x over previous
#include <cuda_runtime.h>

// Fused 2-layer MLP (B=8192, F=256, I=128, O=128), HBM-bound on the 1 GiB input.
//
// R3 design:
//  - NB=2 batches/CTA, grid=4096: halves per-CTA duration -> tail-drain loss 14%->7%.
//  - 8-lane row teams: warp iteration covers 4 f-rows; lane l of group g reads
//    float4 c = j*8+l of row f=base+g. Coalescing preserved (4 x 128B segments per
//    warp-load). Reduction = 3 butterflies within 8 lanes (was 5 across 32),
//    and 12 independent LDG.128 are batched per iteration -> steadier DRAM demand.
//  - __ldcs on the input stream (no reuse, evict-first), __ldg on weights.
//  - __launch_bounds__(256,5): cap 48 regs -> 5 CTAs/SM (62.5% occ).

#define NB 2

__global__ __launch_bounds__(256, 5) void fused_mlp_kernel(
    const float* __restrict__ in,  const float* __restrict__ W1,
    const float* __restrict__ b1,  const float* __restrict__ W2,
    const float* __restrict__ b2,  float* __restrict__ out,
    int B)
{
    __shared__ float h_s[NB][256];

    const int tid  = threadIdx.x;
    const int lane = tid & 31;
    const int warp = tid >> 5;
    const int g    = lane >> 3;   // 0..3 : which row of the 4-row group
    const int l    = lane & 7;    // 0..7 : lane within the 8-lane row team

    const long long b0 = (long long)blockIdx.x * NB;
    const bool v1 = (b0 + 1) < B;

    const float4* __restrict__ xA  = (const float4*)(in + b0 * (256LL * 128));
    const float4* __restrict__ xB  = v1 ? (const float4*)(in + (b0 + 1) * (256LL * 128)) : xA;
    const float4* __restrict__ W1v = (const float4*)W1;

    // ------------------- Stage 1: h[nb][f] -------------------
    // warp owns f in [32*warp, 32*warp+32), 4 rows per iteration.
    #pragma unroll 2
    for (int it = 0; it < 8; ++it) {
        const int f = warp * 32 + it * 4 + g;
        float s0 = 0.0f, s1 = 0.0f;
        #pragma unroll
        for (int j = 0; j < 4; ++j) {
            const int c = f * 32 + j * 8 + l;      // float4 index, shared by W1 & input
            const float4 w = __ldg(&W1v[c]);
            const float4 a = __ldcs(&xA[c]);
            const float4 b = __ldcs(&xB[c]);
            s0 = fmaf(a.x, w.x, fmaf(a.y, w.y, fmaf(a.z, w.z, fmaf(a.w, w.w, s0))));
            s1 = fmaf(b.x, w.x, fmaf(b.y, w.y, fmaf(b.z, w.z, fmaf(b.w, w.w, s1))));
        }
        #pragma unroll
        for (int off = 4; off > 0; off >>= 1) {
            s0 += __shfl_xor_sync(0xFFFFFFFFu, s0, off);
            s1 += __shfl_xor_sync(0xFFFFFFFFu, s1, off);
        }
        if (l == 0) {
            const float bb = b1[f];
            h_s[0][f] = fmaxf(s0 + bb, 0.0f);
            h_s[1][f] = fmaxf(s1 + bb, 0.0f);
        }
    }
    __syncthreads();

    // ------------------- Stage 2: out[nb][o] -------------------
    const float4* __restrict__ W2v = (const float4*)W2;
    const float4* __restrict__ h0  = (const float4*)h_s[0];
    const float4* __restrict__ h1  = (const float4*)h_s[1];

    #pragma unroll
    for (int it = 0; it < 4; ++it) {
        const int o = it * 32 + warp * 4 + g;
        float s0 = 0.0f, s1 = 0.0f;
        #pragma unroll
        for (int j = 0; j < 8; ++j) {
            const int c = j * 8 + l;               // float4 index within the 256-wide row
            const float4 w = __ldg(&W2v[o * 64 + c]);
            const float4 a = h0[c];                // broadcast across the 4 groups
            const float4 b = h1[c];
            s0 = fmaf(a.x, w.x, fmaf(a.y, w.y, fmaf(a.z, w.z, fmaf(a.w, w.w, s0))));
            s1 = fmaf(b.x, w.x, fmaf(b.y, w.y, fmaf(b.z, w.z, fmaf(b.w, w.w, s1))));
        }
        #pragma unroll
        for (int off = 4; off > 0; off >>= 1) {
            s0 += __shfl_xor_sync(0xFFFFFFFFu, s0, off);
            s1 += __shfl_xor_sync(0xFFFFFFFFu, s1, off);
        }
        if (l == 0) {
            const float bb = b2[o];
            out[b0 * 128 + o] = fmaxf(s0 + bb, 0.0f);
            if (v1) out[(b0 + 1) * 128 + o] = fmaxf(s1 + bb, 0.0f);
        }
    }
}

extern "C" void kernel_launch(void* const* d_in, const int* in_sizes, int n_in,
                              void* d_out, int out_size)
{
    const float* in = (const float*)d_in[0];   // [B, 256, 128] fp32
    const float* W1 = (const float*)d_in[1];   // [256, 128]
    const float* b1 = (const float*)d_in[2];   // [256]
    const float* W2 = (const float*)d_in[3];   // [128, 256]
    const float* b2 = (const float*)d_in[4];   // [128]
    float* out = (float*)d_out;                // [B, 128]

    const int B = in_sizes[0] / (256 * 128);
    const int grid = (B + NB - 1) / NB;

    fused_mlp_kernel<<<grid, 256>>>(in, W1, b1, W2, b2, out, B);
}

// round 4
// speedup vs baseline: 1.0502x; 1.0046x over previous
#include <cuda_runtime.h>

// Fused 2-layer MLP (B=8192, F=256, I=128, O=128). HBM-bound: 1 GiB input stream.
//
// R4: persistent CTAs + atomic work queue.
//  - grid = SMs*5 resident CTAs; tiles (1 batch row each) pulled from a global
//    atomic counter -> end-of-kernel skew <= 1 tile (~1.5us), vs ~9% triangular
//    drain with a 4096-CTA launch. Also neutralizes the MLP_p1~12 cross-CTA
//    L1tex-queue completion spread (late tiles get stolen).
//  - Weights stay L1-resident across a CTA's ~11 tiles (L1D persists within
//    launch); input uses __ldcs (evict-first) to protect that residency.
//  - 8-lane row teams from R3 kept: coalesced 128B segments, 3-deep reductions.

__device__ int g_tile_counter;

__global__ void init_counter_kernel() { g_tile_counter = 0; }

__global__ __launch_bounds__(256, 5) void fused_mlp_persistent(
    const float* __restrict__ in,  const float* __restrict__ W1,
    const float* __restrict__ b1,  const float* __restrict__ W2,
    const float* __restrict__ b2,  float* __restrict__ out,
    int n_tiles)
{
    __shared__ float h_s[256];
    __shared__ int   s_tile;

    const int tid  = threadIdx.x;
    const int lane = tid & 31;
    const int warp = tid >> 5;
    const int g    = lane >> 3;   // row within 4-row group
    const int l    = lane & 7;    // lane within 8-lane row team

    const float4* __restrict__ W1v = (const float4*)W1;
    const float4* __restrict__ W2v = (const float4*)W2;

    for (;;) {
        if (tid == 0) s_tile = atomicAdd(&g_tile_counter, 1);
        __syncthreads();                   // also orders prev stage-2 reads vs next h_s writes
        const int t = s_tile;
        if (t >= n_tiles) break;

        const float4* __restrict__ x = (const float4*)(in + (long long)t * (256 * 128));

        // ---------- Stage 1: h[f] = relu(dot(x[f,:], W1[f,:]) + b1[f]) ----------
        #pragma unroll 2
        for (int it = 0; it < 8; ++it) {
            const int f = warp * 32 + it * 4 + g;
            float s = 0.0f;
            #pragma unroll
            for (int j = 0; j < 4; ++j) {
                const int c = f * 32 + j * 8 + l;   // float4 index (row stride 32)
                const float4 w = __ldg(&W1v[c]);
                const float4 a = __ldcs(&x[c]);
                s = fmaf(a.x, w.x, fmaf(a.y, w.y, fmaf(a.z, w.z, fmaf(a.w, w.w, s))));
            }
            #pragma unroll
            for (int off = 4; off > 0; off >>= 1)
                s += __shfl_xor_sync(0xFFFFFFFFu, s, off);
            if (l == 0)
                h_s[f] = fmaxf(s + b1[f], 0.0f);
        }
        __syncthreads();

        // ---------- Stage 2: out[o] = relu(dot(h, W2[o,:]) + b2[o]) ----------
        const float4* __restrict__ hv = (const float4*)h_s;
        #pragma unroll
        for (int it = 0; it < 4; ++it) {
            const int o = it * 32 + warp * 4 + g;
            float s = 0.0f;
            #pragma unroll
            for (int j = 0; j < 8; ++j) {
                const int c = j * 8 + l;            // float4 index within 256-wide row
                const float4 w = __ldg(&W2v[o * 64 + c]);
                const float4 a = hv[c];             // smem broadcast across groups
                s = fmaf(a.x, w.x, fmaf(a.y, w.y, fmaf(a.z, w.z, fmaf(a.w, w.w, s))));
            }
            #pragma unroll
            for (int off = 4; off > 0; off >>= 1)
                s += __shfl_xor_sync(0xFFFFFFFFu, s, off);
            if (l == 0)
                out[(long long)t * 128 + o] = fmaxf(s + b2[o], 0.0f);
        }
        // no sync needed here: loop-top __syncthreads orders h_s reuse
    }
}

extern "C" void kernel_launch(void* const* d_in, const int* in_sizes, int n_in,
                              void* d_out, int out_size)
{
    const float* in = (const float*)d_in[0];   // [B, 256, 128] fp32
    const float* W1 = (const float*)d_in[1];   // [256, 128]
    const float* b1 = (const float*)d_in[2];   // [256]
    const float* W2 = (const float*)d_in[3];   // [128, 256]
    const float* b2 = (const float*)d_in[4];   // [128]
    float* out = (float*)d_out;                // [B, 128]

    const int B = in_sizes[0] / (256 * 128);   // tiles = batch rows

    int sms = 148;
    cudaDeviceGetAttribute(&sms, cudaDevAttrMultiProcessorCount, 0);
    int grid = sms * 5;
    if (grid > B) grid = B;

    init_counter_kernel<<<1, 1>>>();
    fused_mlp_persistent<<<grid, 256>>>(in, W1, b1, W2, b2, out, B);
}